// round 15
// baseline (speedup 1.0000x reference)
#include <cuda_runtime.h>
#include <cuda_fp16.h>
#include <cstdint>

#define B_  4
#define LQ  512
#define LK  512
#define DQ  256
#define DC  256
#define H_  128

typedef unsigned long long ull;

// Scratch (__device__ globals: allocation-free rule)
__device__ __half g_qph [B_ * LQ * H_];       // [row][h] : query proj + bq (fp16)
__device__ __half g_c2h [B_ * H_ * LK];       // [b][h][k]: 2*(ctx proj + bc) (fp16)
__device__ ull    g_WT2 [2][DQ / 2][H_];      // [m][d2][h] packed W columns

// ---------- f32x2 helpers ----------
__device__ __forceinline__ ull pk(float a, float b) {
    ull r; asm("mov.b64 %0, {%1, %2};" : "=l"(r) : "f"(a), "f"(b)); return r;
}
__device__ __forceinline__ void upk(ull v, float& a, float& b) {
    asm("mov.b64 {%0, %1}, %2;" : "=f"(a), "=f"(b) : "l"(v));
}
__device__ __forceinline__ ull add2(ull a, ull b) {
    ull r; asm("add.rn.f32x2 %0, %1, %2;" : "=l"(r) : "l"(a), "l"(b)); return r;
}
__device__ __forceinline__ ull fma2(ull a, ull b, ull c) {
    ull r; asm("fma.rn.f32x2 %0, %1, %2, %3;" : "=l"(r) : "l"(a), "l"(b), "l"(c)); return r;
}
__device__ __forceinline__ __half2 tanh2(__half2 v) {
    uint32_t x = *reinterpret_cast<uint32_t*>(&v), y;
    asm("tanh.approx.f16x2 %0, %1;" : "=r"(y) : "r"(x));
    return *reinterpret_cast<__half2*>(&y);
}

// ---------------------------------------------------------------------------
// Kernel 0: pack-transpose W -> g_WT2[m][d2][h]
// ---------------------------------------------------------------------------
__global__ __launch_bounds__(256) void wt_kernel(
    const float* __restrict__ Wq, const float* __restrict__ Wc)
{
    const int m = blockIdx.y;
    const float* W = m ? Wc : Wq;
    const int idx = blockIdx.x * 256 + threadIdx.x;
    const int d2 = idx >> 7, h = idx & 127;
    g_WT2[m][d2][h] = pk(W[h * DQ + 2 * d2], W[h * DQ + 2 * d2 + 1]);
}

// ---------------------------------------------------------------------------
// Kernel 1: projections (R3 core), fp16 outputs for the fused hot loop.
// ---------------------------------------------------------------------------
__global__ __launch_bounds__(256) void proj_kernel(
    const float* __restrict__ query, const float* __restrict__ context,
    const float* __restrict__ bq, const float* __restrict__ bc)
{
    __shared__ float insh[16][256];

    const int m    = blockIdx.x >> 7;
    const int tile = blockIdx.x & 127;
    const float* in   = m ? context : query;
    const float* bias = m ? bc : bq;
    const int t  = threadIdx.x;
    const int r0 = tile * 16;

    {
        const float4* src = (const float4*)(in + (size_t)r0 * 256);
        float4* dst = (float4*)insh;
        #pragma unroll
        for (int i = t; i < 16 * 64; i += 256) dst[i] = src[i];
    }
    __syncthreads();

    const int h  = t & 127;
    const int rg = t >> 7;
    const float bb = bias[h];
    ull acc[8];
    #pragma unroll
    for (int j = 0; j < 8; j++) acc[j] = pk(bb, 0.0f);

    const ull* wp = &g_WT2[m][0][h];
    #pragma unroll 4
    for (int d4 = 0; d4 < 64; d4++) {
        const ull w01 = wp[(2 * d4)     * H_];
        const ull w23 = wp[(2 * d4 + 1) * H_];
        #pragma unroll
        for (int j = 0; j < 8; j++) {
            const ulonglong2 q2 = *(const ulonglong2*)&insh[rg * 8 + j][d4 * 4];
            acc[j] = fma2(w01, q2.x, acc[j]);
            acc[j] = fma2(w23, q2.y, acc[j]);
        }
    }

    #pragma unroll
    for (int j = 0; j < 8; j++) {
        float lo, hi; upk(acc[j], lo, hi);
        const float s = lo + hi;
        const int row = r0 + rg * 8 + j;
        if (m == 0) {
            g_qph[(size_t)row * H_ + h] = __float2half(s);
        } else {
            const int b = row >> 9, k = row & 511;
            g_c2h[((size_t)b * H_ + h) * LK + k] = __float2half(2.0f * s);
        }
    }
}

// ---------------------------------------------------------------------------
// Kernel 2: FUSED scores + softmax + (attn @ context).
// 256 CTAs = (b, 8q-tile), 256 threads. Smem ~37KB (up from 48KB) so more
// CTAs are co-resident: CTAs in MUFU-bound phase 1 overlap with CTAs in
// fma/LDG-bound phase 3 on the same SM.
// ---------------------------------------------------------------------------
__global__ __launch_bounds__(256) void fused_kernel(
    const float* __restrict__ Wv,
    const float* __restrict__ context,
    float* __restrict__ out)
{
    __shared__ float   sc  [8][512];      // 16KB: scores -> packed attn ull[512][4]
    __shared__ float   c_sh[16][260];     // 16.6KB: ctx tile (phase 3, BK=16)
    __shared__ __half2 qsh [8 * H_];      // 4KB
    __shared__ __half2 wvh [H_];          // 0.5KB

    const int bx = blockIdx.x;
    const int b  = bx >> 6;                // 64 tiles per batch
    const int q0 = (bx & 63) * 8;
    const int t  = threadIdx.x;

    // ---- load qp (broadcast pairs) + Wv ----
    #pragma unroll
    for (int i = t; i < 8 * H_; i += 256) {
        const int q = i >> 7, h = i & 127;
        qsh[i] = __half2half2(g_qph[((size_t)(b * LQ + q0 + q)) * H_ + h]);
    }
    if (t < H_) wvh[t] = __float2half2_rn(Wv[t]);
    __syncthreads();

    // ---- Phase 1: scores (fp16 hot loop; R4-verified cp[h*128] addressing) ----
    {
        const int kt = t & 127;           // k-quad: k = 4kt..4kt+3
        const int qg = (t >> 7) * 4;      // q-offset 0 or 4 (4 q's each)
        const ull* cp = (const ull*)(g_c2h + (size_t)b * H_ * LK) + kt;

        const __half2 hz = __floats2half2_rn(0.0f, 0.0f);
        ull facc[4][2];
        __half2 wacc[4][2];
        #pragma unroll
        for (int qi = 0; qi < 4; qi++) {
            facc[qi][0] = 0ULL; facc[qi][1] = 0ULL;
            wacc[qi][0] = hz;   wacc[qi][1] = hz;
        }

        #pragma unroll 2
        for (int hw = 0; hw < 32; hw++) {         // 32 windows of 4 h
            ull cc[4];
            #pragma unroll
            for (int j = 0; j < 4; j++)           // batch LDGs (MLP>=4)
                cc[j] = cp[(size_t)(hw * 4 + j) * 128];

            #pragma unroll
            for (int j = 0; j < 4; j++) {
                const int h = hw * 4 + j;
                const __half2 c01 = ((const __half2*)&cc[j])[0];
                const __half2 c23 = ((const __half2*)&cc[j])[1];
                const __half2 wv = wvh[h];
                #pragma unroll
                for (int qi = 0; qi < 4; qi++) {
                    const __half2 qq = qsh[(qg + qi) * H_ + h];
                    wacc[qi][0] = __hfma2(tanh2(__hadd2(qq, c01)), wv, wacc[qi][0]);
                    wacc[qi][1] = __hfma2(tanh2(__hadd2(qq, c23)), wv, wacc[qi][1]);
                }
            }
            #pragma unroll
            for (int qi = 0; qi < 4; qi++) {
                #pragma unroll
                for (int p = 0; p < 2; p++) {
                    const float2 f = __half22float2(wacc[qi][p]);
                    facc[qi][p] = add2(pk(f.x, f.y), facc[qi][p]);
                    wacc[qi][p] = hz;
                }
            }
        }

        #pragma unroll
        for (int qi = 0; qi < 4; qi++) {
            float s0, s1, s2, s3;
            upk(facc[qi][0], s0, s1);
            upk(facc[qi][1], s2, s3);
            *(float4*)&sc[qg + qi][kt * 4] = make_float4(s0, s1, s2, s3);
        }
    }
    __syncthreads();

    // ---- Phase 2: softmax (warp w -> q0 + w) ----
    {
        const int w = t >> 5, lane = t & 31;
        float e[16];
        float mx = -1e30f;
        #pragma unroll
        for (int j = 0; j < 16; j++) {
            e[j] = sc[w][lane + j * 32];
            mx = fmaxf(mx, e[j]);
        }
        #pragma unroll
        for (int off = 16; off > 0; off >>= 1)
            mx = fmaxf(mx, __shfl_xor_sync(0xffffffffu, mx, off));
        float s = 0.0f;
        #pragma unroll
        for (int j = 0; j < 16; j++) { e[j] = __expf(e[j] - mx); s += e[j]; }
        #pragma unroll
        for (int off = 16; off > 0; off >>= 1)
            s += __shfl_xor_sync(0xffffffffu, s, off);
        const float inv = 1.0f / s;
        #pragma unroll
        for (int j = 0; j < 16; j++) sc[w][lane + j * 32] = e[j] * inv;
    }
    __syncthreads();

    // ---- Phase 2.5: repack attn -> at2[k][ty] = (attn[2ty][k], attn[2ty+1][k]) ----
    {
        ull r[8];
        #pragma unroll
        for (int j = 0; j < 8; j++) {
            const int e   = j * 256 + t;       // linear packed index = k*4 + ty
            const int k   = e >> 2;
            const int ty2 = (e & 3) * 2;
            r[j] = pk(sc[ty2][k], sc[ty2 + 1][k]);
        }
        __syncthreads();
        #pragma unroll
        for (int j = 0; j < 8; j++)
            ((ull*)sc)[j * 256 + t] = r[j];    // conflict-free (8B stride)
    }
    __syncthreads();

    // ---- Phase 3: out = attn @ ctx (BK=16, 32 stages, reg prefetch) ----
    {
        const int tx = t & 63;                // d-quad: d = tx*4
        const int ty = t >> 6;                // q-pair: q0 + 2ty, +1 (warp-uniform)
        const int cr = t >> 4, cf = t & 15;   // ctx loader: row cr (16), 4 f4/row

        const float4* cg  = (const float4*)(context + (size_t)b * LK * DC);
        const ull*    at2 = (const ull*)sc;

        float4 pf[4];
        #pragma unroll
        for (int j = 0; j < 4; j++)
            pf[j] = cg[(size_t)cr * 64 + cf + 16 * j];

        ull acc[4];
        acc[0] = acc[1] = acc[2] = acc[3] = 0ULL;

        #pragma unroll 1
        for (int s = 0; s < 32; s++) {
            #pragma unroll
            for (int j = 0; j < 4; j++)
                *(float4*)&c_sh[cr][(cf + 16 * j) * 4] = pf[j];
            __syncthreads();

            if (s < 31) {                     // prefetch next tile (overlaps compute)
                #pragma unroll
                for (int j = 0; j < 4; j++)
                    pf[j] = cg[(size_t)((s + 1) * 16 + cr) * 64 + cf + 16 * j];
            }

            #pragma unroll
            for (int k = 0; k < 16; k++) {
                const ull a2 = at2[(s * 16 + k) * 4 + ty];        // broadcast
                const float4 c4 = *(const float4*)&c_sh[k][tx * 4];
                acc[0] = fma2(a2, pk(c4.x, c4.x), acc[0]);
                acc[1] = fma2(a2, pk(c4.y, c4.y), acc[1]);
                acc[2] = fma2(a2, pk(c4.z, c4.z), acc[2]);
                acc[3] = fma2(a2, pk(c4.w, c4.w), acc[3]);
            }
            __syncthreads();
        }

        float o0[4], o1[4];
        #pragma unroll
        for (int d = 0; d < 4; d++) upk(acc[d], o0[d], o1[d]);

        float4* dst0 = (float4*)(out + ((size_t)b * LQ + q0 + 2 * ty)     * DC + tx * 4);
        float4* dst1 = (float4*)(out + ((size_t)b * LQ + q0 + 2 * ty + 1) * DC + tx * 4);
        *dst0 = make_float4(o0[0], o0[1], o0[2], o0[3]);
        *dst1 = make_float4(o1[0], o1[1], o1[2], o1[3]);
    }
}

// ---------------------------------------------------------------------------
extern "C" void kernel_launch(void* const* d_in, const int* in_sizes, int n_in,
                              void* d_out, int out_size)
{
    const float* query   = (const float*)d_in[0];
    const float* context = (const float*)d_in[1];
    const float* Wq      = (const float*)d_in[2];
    const float* bq      = (const float*)d_in[3];
    const float* Wc      = (const float*)d_in[4];
    const float* bc      = (const float*)d_in[5];
    const float* Wv      = (const float*)d_in[6];
    // d_in[7] = bv : constant pre-softmax shift, mathematically a no-op.

    wt_kernel   <<<dim3(64, 2), 256>>>(Wq, Wc);
    proj_kernel <<<256, 256>>>(query, context, bq, bc);
    fused_kernel<<<256, 256>>>(Wv, context, (float*)d_out);
}

// round 16
// speedup vs baseline: 1.1921x; 1.1921x over previous
#include <cuda_runtime.h>
#include <cuda_fp16.h>
#include <cstdint>

#define B_  4
#define LQ  512
#define LK  512
#define DQ  256
#define DC  256
#define H_  128

typedef unsigned long long ull;

// Scratch (__device__ globals: allocation-free rule)
__device__ __half g_qph [B_ * LQ * H_];       // [row][h] : query proj + bq (fp16)
__device__ __half g_c2h [B_ * H_ * LK];       // [b][h][k]: 2*(ctx proj + bc) (fp16)
__device__ float  g_attn[B_ * LQ * LK];       // softmax weights
__device__ ull    g_WT2 [2][DQ / 2][H_];      // [m][d2][h] packed W columns

// ---------- f32x2 helpers ----------
__device__ __forceinline__ ull pk(float a, float b) {
    ull r; asm("mov.b64 %0, {%1, %2};" : "=l"(r) : "f"(a), "f"(b)); return r;
}
__device__ __forceinline__ void upk(ull v, float& a, float& b) {
    asm("mov.b64 {%0, %1}, %2;" : "=f"(a), "=f"(b) : "l"(v));
}
__device__ __forceinline__ ull add2(ull a, ull b) {
    ull r; asm("add.rn.f32x2 %0, %1, %2;" : "=l"(r) : "l"(a), "l"(b)); return r;
}
__device__ __forceinline__ ull fma2(ull a, ull b, ull c) {
    ull r; asm("fma.rn.f32x2 %0, %1, %2, %3;" : "=l"(r) : "l"(a), "l"(b), "l"(c)); return r;
}
__device__ __forceinline__ __half2 tanh2(__half2 v) {
    uint32_t x = *reinterpret_cast<uint32_t*>(&v), y;
    asm("tanh.approx.f16x2 %0, %1;" : "=r"(y) : "r"(x));
    return *reinterpret_cast<__half2*>(&y);
}

// ---------------------------------------------------------------------------
// Kernel 0: pack-transpose W -> g_WT2[m][d2][h]
// ---------------------------------------------------------------------------
__global__ __launch_bounds__(256) void wt_kernel(
    const float* __restrict__ Wq, const float* __restrict__ Wc)
{
    const int m = blockIdx.y;
    const float* W = m ? Wc : Wq;
    const int idx = blockIdx.x * 256 + threadIdx.x;
    const int d2 = idx >> 7, h = idx & 127;
    g_WT2[m][d2][h] = pk(W[h * DQ + 2 * d2], W[h * DQ + 2 * d2 + 1]);
}

// ---------------------------------------------------------------------------
// Kernel 1: projections (R3 core), fp16 outputs for the scores hot loop.
// ---------------------------------------------------------------------------
__global__ __launch_bounds__(256) void proj_kernel(
    const float* __restrict__ query, const float* __restrict__ context,
    const float* __restrict__ bq, const float* __restrict__ bc)
{
    __shared__ float insh[16][256];

    const int m    = blockIdx.x >> 7;
    const int tile = blockIdx.x & 127;
    const float* in   = m ? context : query;
    const float* bias = m ? bc : bq;
    const int t  = threadIdx.x;
    const int r0 = tile * 16;

    {
        const float4* src = (const float4*)(in + (size_t)r0 * 256);
        float4* dst = (float4*)insh;
        #pragma unroll
        for (int i = t; i < 16 * 64; i += 256) dst[i] = src[i];
    }
    __syncthreads();

    const int h  = t & 127;
    const int rg = t >> 7;
    const float bb = bias[h];
    ull acc[8];
    #pragma unroll
    for (int j = 0; j < 8; j++) acc[j] = pk(bb, 0.0f);

    const ull* wp = &g_WT2[m][0][h];
    #pragma unroll 4
    for (int d4 = 0; d4 < 64; d4++) {
        const ull w01 = wp[(2 * d4)     * H_];
        const ull w23 = wp[(2 * d4 + 1) * H_];
        #pragma unroll
        for (int j = 0; j < 8; j++) {
            const ulonglong2 q2 = *(const ulonglong2*)&insh[rg * 8 + j][d4 * 4];
            acc[j] = fma2(w01, q2.x, acc[j]);
            acc[j] = fma2(w23, q2.y, acc[j]);
        }
    }

    #pragma unroll
    for (int j = 0; j < 8; j++) {
        float lo, hi; upk(acc[j], lo, hi);
        const float s = lo + hi;
        const int row = r0 + rg * 8 + j;
        if (m == 0) {
            g_qph[(size_t)row * H_ + h] = __float2half(s);
        } else {
            const int b = row >> 9, k = row & 511;
            g_c2h[((size_t)b * H_ + h) * LK + k] = __float2half(2.0f * s);
        }
    }
}

// ---------------------------------------------------------------------------
// Kernel 2: scores + fused softmax at R1-PROVEN OCCUPANCY.
// 1024 CTAs = (b, 2q), 256 threads, ~5.5KB smem -> ~6 CTAs/SM, ~48 warps/SM.
// Thread: kt = t&127 -> k = 4kt..4kt+3 (one fp16 LDG.64 per h); qh = t>>7.
// fp16 hot loop (HADD2 + tanh2 + HFMA2), window-4 flush to f32x2.
// Addressing: g_c2h row = 512 halfs = 128 ull (R4/R13-verified).
// bv dropped (softmax-invariant).
// ---------------------------------------------------------------------------
__global__ __launch_bounds__(256) void scores_kernel(const float* __restrict__ Wv)
{
    __shared__ __half2 qsh[2][H_];    // (qp, qp) per (q, h) : 1KB
    __shared__ __half2 wvh[H_];       // (Wv, Wv)            : 0.5KB
    __shared__ float   sc[2][LK];     // scores              : 4KB

    const int tile = blockIdx.x;          // 0..1023
    const int b  = tile >> 8;             // 256 tiles per batch
    const int q0 = (tile & 255) * 2;
    const int t  = threadIdx.x;

    if (t < 2 * H_) {
        const int q = t >> 7, h = t & 127;
        qsh[q][h] = __half2half2(g_qph[((size_t)(b * LQ + q0 + q)) * H_ + h]);
    }
    if (t < H_) wvh[t] = __float2half2_rn(Wv[t]);
    __syncthreads();

    const int kt = t & 127;               // k-quad: k = 4kt..4kt+3
    const int qh = t >> 7;                // this thread's q (0 or 1)
    const ull* cp = (const ull*)(g_c2h + (size_t)b * H_ * LK) + kt;

    const __half2 hz = __floats2half2_rn(0.0f, 0.0f);
    ull facc0 = 0ULL, facc1 = 0ULL;
    __half2 wacc0 = hz, wacc1 = hz;

    #pragma unroll 2
    for (int hw = 0; hw < 32; hw++) {     // 32 windows of 4 h
        ull cc[4];
        #pragma unroll
        for (int j = 0; j < 4; j++)       // batch LDGs (MLP=4)
            cc[j] = cp[(size_t)(hw * 4 + j) * 128];

        #pragma unroll
        for (int j = 0; j < 4; j++) {
            const int h = hw * 4 + j;
            const __half2 c01 = ((const __half2*)&cc[j])[0];
            const __half2 c23 = ((const __half2*)&cc[j])[1];
            const __half2 qq = qsh[qh][h];               // broadcast LDS
            const __half2 wv = wvh[h];                   // broadcast LDS
            wacc0 = __hfma2(tanh2(__hadd2(qq, c01)), wv, wacc0);
            wacc1 = __hfma2(tanh2(__hadd2(qq, c23)), wv, wacc1);
        }
        // flush fp16 window -> f32x2
        {
            const float2 f0 = __half22float2(wacc0);
            const float2 f1 = __half22float2(wacc1);
            facc0 = add2(pk(f0.x, f0.y), facc0);
            facc1 = add2(pk(f1.x, f1.y), facc1);
            wacc0 = hz; wacc1 = hz;
        }
    }

    {
        float s0, s1, s2, s3;
        upk(facc0, s0, s1); upk(facc1, s2, s3);
        *(float4*)&sc[qh][kt * 4] = make_float4(s0, s1, s2, s3);
    }
    __syncthreads();

    // fused softmax: warp w -> q0 + w (w in {0,1}); other warps exit
    const int w = t >> 5, lane = t & 31;
    if (w < 2) {
        float e[16];
        float mx = -1e30f;
        #pragma unroll
        for (int j = 0; j < 16; j++) {
            e[j] = sc[w][lane + j * 32];
            mx = fmaxf(mx, e[j]);
        }
        #pragma unroll
        for (int off = 16; off > 0; off >>= 1)
            mx = fmaxf(mx, __shfl_xor_sync(0xffffffffu, mx, off));
        float s = 0.0f;
        #pragma unroll
        for (int j = 0; j < 16; j++) { e[j] = __expf(e[j] - mx); s += e[j]; }
        #pragma unroll
        for (int off = 16; off > 0; off >>= 1)
            s += __shfl_xor_sync(0xffffffffu, s, off);
        const float inv = 1.0f / s;
        float* dst = g_attn + ((size_t)b * LQ + q0 + w) * LK;
        #pragma unroll
        for (int j = 0; j < 16; j++) dst[lane + j * 32] = e[j] * inv;  // coalesced
    }
}

// ---------------------------------------------------------------------------
// Kernel 3: out = attn @ context — exact R3 smem GEMM (proven 21.3us).
// BM=64, BN=64, BK=32. 128 CTAs. Register-prefetch pipeline.
// ---------------------------------------------------------------------------
__global__ __launch_bounds__(256) void out_kernel(
    const float* __restrict__ context, float* __restrict__ out)
{
    __shared__ float a_sh[32][68];    // [k][q] transposed attn tile
    __shared__ float c_sh[32][68];    // [k][d] ctx tile

    const int bx = blockIdx.x;        // 0..127
    const int b  = bx >> 5;
    const int q0 = ((bx >> 2) & 7) * 64;
    const int d0 = (bx & 3) * 64;
    const int t  = threadIdx.x;
    const int tx = t & 15;            // d-group: d0 + tx*4
    const int ty = t >> 4;            // q-group: q0 + ty*4

    const int ar = t >> 3, ac4 = t & 7;     // attn: rows ar, ar+32
    const int cr = t >> 4, cc4 = t & 15;    // ctx:  rows cr, cr+16

    const float4* ag = (const float4*)(g_attn + ((size_t)b * LQ + q0) * LK);
    const float4* cg = (const float4*)(context + (size_t)b * LK * DC + d0);

    float4 pa0 = ag[(size_t)ar * 128 + ac4];
    float4 pa1 = ag[(size_t)(ar + 32) * 128 + ac4];
    float4 pc0 = cg[(size_t)cr * 64 + cc4];
    float4 pc1 = cg[(size_t)(cr + 16) * 64 + cc4];

    ull acc[2][4];
    #pragma unroll
    for (int p = 0; p < 2; p++)
        #pragma unroll
        for (int d = 0; d < 4; d++) acc[p][d] = 0ULL;

    #pragma unroll 1
    for (int s = 0; s < 16; s++) {
        __syncthreads();
        a_sh[ac4 * 4 + 0][ar] = pa0.x;
        a_sh[ac4 * 4 + 1][ar] = pa0.y;
        a_sh[ac4 * 4 + 2][ar] = pa0.z;
        a_sh[ac4 * 4 + 3][ar] = pa0.w;
        a_sh[ac4 * 4 + 0][ar + 32] = pa1.x;
        a_sh[ac4 * 4 + 1][ar + 32] = pa1.y;
        a_sh[ac4 * 4 + 2][ar + 32] = pa1.z;
        a_sh[ac4 * 4 + 3][ar + 32] = pa1.w;
        *(float4*)&c_sh[cr][cc4 * 4]      = pc0;
        *(float4*)&c_sh[cr + 16][cc4 * 4] = pc1;
        __syncthreads();

        if (s < 15) {
            const int k4 = (s + 1) * 8;
            const int kr = (s + 1) * 32;
            pa0 = ag[(size_t)ar * 128 + k4 + ac4];
            pa1 = ag[(size_t)(ar + 32) * 128 + k4 + ac4];
            pc0 = cg[(size_t)(kr + cr) * 64 + cc4];
            pc1 = cg[(size_t)(kr + cr + 16) * 64 + cc4];
        }

        #pragma unroll
        for (int k = 0; k < 32; k++) {
            const ulonglong2 a2 = *(const ulonglong2*)&a_sh[k][ty * 4];
            const float4 c4 = *(const float4*)&c_sh[k][tx * 4];
            const ull cx = pk(c4.x, c4.x);
            const ull cy = pk(c4.y, c4.y);
            const ull cz = pk(c4.z, c4.z);
            const ull cw = pk(c4.w, c4.w);
            acc[0][0] = fma2(a2.x, cx, acc[0][0]);
            acc[0][1] = fma2(a2.x, cy, acc[0][1]);
            acc[0][2] = fma2(a2.x, cz, acc[0][2]);
            acc[0][3] = fma2(a2.x, cw, acc[0][3]);
            acc[1][0] = fma2(a2.y, cx, acc[1][0]);
            acc[1][1] = fma2(a2.y, cy, acc[1][1]);
            acc[1][2] = fma2(a2.y, cz, acc[1][2]);
            acc[1][3] = fma2(a2.y, cw, acc[1][3]);
        }
    }

    float o[4][4];
    #pragma unroll
    for (int p = 0; p < 2; p++)
        #pragma unroll
        for (int d = 0; d < 4; d++)
            upk(acc[p][d], o[2 * p][d], o[2 * p + 1][d]);

    #pragma unroll
    for (int qi = 0; qi < 4; qi++) {
        float4* dst = (float4*)(out + ((size_t)b * LQ + q0 + ty * 4 + qi) * DC
                                + d0 + tx * 4);
        *dst = make_float4(o[qi][0], o[qi][1], o[qi][2], o[qi][3]);
    }
}

// ---------------------------------------------------------------------------
extern "C" void kernel_launch(void* const* d_in, const int* in_sizes, int n_in,
                              void* d_out, int out_size)
{
    const float* query   = (const float*)d_in[0];
    const float* context = (const float*)d_in[1];
    const float* Wq      = (const float*)d_in[2];
    const float* bq      = (const float*)d_in[3];
    const float* Wc      = (const float*)d_in[4];
    const float* bc      = (const float*)d_in[5];
    const float* Wv      = (const float*)d_in[6];
    // d_in[7] = bv : constant pre-softmax shift, mathematically a no-op.

    wt_kernel    <<<dim3(64, 2), 256>>>(Wq, Wc);
    proj_kernel  <<<256, 256>>>(query, context, bq, bc);
    scores_kernel<<<1024, 256>>>(Wv);
    out_kernel   <<<128, 256>>>(context, (float*)d_out);
}